// round 9
// baseline (speedup 1.0000x reference)
#include <cuda_runtime.h>
#include <cuda_bf16.h>
#include <cstdint>
#include <math.h>

// Problem constants
#define NROWS 2048
#define VDIM  50257
#define VPAD  50272   // bf16 row stride
#define H_S   2048
#define H_T   4096

// Scratch (static device allocations)
__device__ __nv_bfloat16 g_logits_s[(size_t)NROWS * VPAD];  // 206 MB
__device__ __nv_bfloat16 g_logits_t[(size_t)NROWS * VPAD];  // 206 MB
__device__ __nv_bfloat16 g_Ws_bf[(size_t)VDIM * H_S];       // 206 MB
__device__ __nv_bfloat16 g_Wt_bf[(size_t)VDIM * H_T];       // 412 MB
__device__ __nv_bfloat16 g_as_bf[(size_t)NROWS * H_S];
__device__ __nv_bfloat16 g_at_bf[(size_t)NROWS * H_T];
__device__ float g_row_ce[NROWS];
__device__ float g_row_valid[NROWS];
__device__ float g_row_kls[NROWS];
__device__ float g_row_klt[NROWS];

// ---------------------------------------------------------------------------
// Helpers
// ---------------------------------------------------------------------------
__device__ __forceinline__ uint32_t swz(uint32_t row, uint32_t chunk) {
    // 128-byte logical rows (64 bf16), 16B chunks, XOR swizzle
    return row * 128u + ((chunk ^ (row & 7u)) << 4);
}
__device__ __forceinline__ void cp16(uint32_t saddr, const void* gaddr) {
    asm volatile("cp.async.cg.shared.global [%0], [%1], 16;\n"
                 :: "r"(saddr), "l"(gaddr) : "memory");
}

// ---------------------------------------------------------------------------
// fp32 -> bf16 (lossless: inputs are fp32-widened bf16).  2 x float4 / iter.
// ---------------------------------------------------------------------------
__global__ __launch_bounds__(256) void cvt_kernel(
    const float* __restrict__ src, __nv_bfloat16* __restrict__ dst, size_t n4)
{
    const size_t stride = (size_t)gridDim.x * 256;
    for (size_t i = (size_t)blockIdx.x * 256 + threadIdx.x; i < n4; i += 2 * stride) {
        size_t i2 = i + stride;
        float4 v0 = *(const float4*)(src + i * 4);
        if (i2 < n4) {
            float4 v1 = *(const float4*)(src + i2 * 4);
            __nv_bfloat162 lo1 = __floats2bfloat162_rn(v1.x, v1.y);
            __nv_bfloat162 hi1 = __floats2bfloat162_rn(v1.z, v1.w);
            *(uint2*)(dst + i2 * 4) = make_uint2(*(uint32_t*)&lo1, *(uint32_t*)&hi1);
        }
        __nv_bfloat162 lo0 = __floats2bfloat162_rn(v0.x, v0.y);
        __nv_bfloat162 hi0 = __floats2bfloat162_rn(v0.z, v0.w);
        *(uint2*)(dst + i * 4) = make_uint2(*(uint32_t*)&lo0, *(uint32_t*)&hi0);
    }
}

// ---------------------------------------------------------------------------
// GEMM: C[n,v] = sum_h A[n,h]*B[v,h]  (bf16 in, fp32 accum, bf16 out)
// CTA tile 128(M) x 256(N) x 64(K), 8 warps (2x4), warp tile 64x64.
// 3-stage cp.async pipeline; A via ldmatrix.x4, B via ldmatrix.x4 (2 n-groups
// per instr, mirror of the validated A mapping).  k16 mma.
// SMEM: stage s at s*49152 (A 16KB, B 32KB); 3 stages = 147456 B.
// ---------------------------------------------------------------------------
__global__ __launch_bounds__(256, 1) void gemm_bf16_kernel(
    const __nv_bfloat16* __restrict__ A,   // [NROWS, H]
    const __nv_bfloat16* __restrict__ B,   // [VDIM, H]
    __nv_bfloat16* __restrict__ C,         // [NROWS, VPAD]
    int H)
{
    extern __shared__ char smem[];
    const uint32_t sbase = (uint32_t)__cvta_generic_to_shared(smem);

    const int tid   = threadIdx.x;
    const int lane  = tid & 31;
    const int warp  = tid >> 5;
    const int warp_m = warp >> 2;   // 0..1  (64-row M slice)
    const int warp_n = warp & 3;    // 0..3  (64-col N slice)
    const int m0 = blockIdx.x * 128;
    const int v0 = blockIdx.y * 256;

    float acc[4][8][4];
    #pragma unroll
    for (int i = 0; i < 4; i++)
        #pragma unroll
        for (int j = 0; j < 8; j++)
            #pragma unroll
            for (int k = 0; k < 4; k++) acc[i][j][k] = 0.f;

    const int ktiles = H >> 6;
    const int lr = tid >> 3;    // 0..31
    const int lc = tid & 7;     // 16B chunk 0..7

    size_t aoff[4], boff[8];
    #pragma unroll
    for (int j = 0; j < 4; j++)
        aoff[j] = (size_t)(m0 + lr + j * 32) * H;
    #pragma unroll
    for (int j = 0; j < 8; j++) {
        int vr = v0 + lr + j * 32;
        if (vr > VDIM - 1) vr = VDIM - 1;   // clamp; clamped rows never stored
        boff[j] = (size_t)vr * H;
    }

    auto load_stage = [&](int slot, int kt) {
        const int k0 = kt * 64;
        const uint32_t aB = sbase + slot * 49152;
        const uint32_t bB = aB + 16384;
        #pragma unroll
        for (int j = 0; j < 4; j++)
            cp16(aB + swz(lr + j * 32, lc), A + aoff[j] + k0 + lc * 8);
        #pragma unroll
        for (int j = 0; j < 8; j++)
            cp16(bB + swz(lr + j * 32, lc), B + boff[j] + k0 + lc * 8);
        asm volatile("cp.async.commit_group;\n" ::: "memory");
    };

    // Prologue: 2 stages in flight
    load_stage(0, 0);
    if (ktiles > 1) load_stage(1, 1);

    for (int kt = 0; kt < ktiles; kt++) {
        if (kt + 1 < ktiles)
            asm volatile("cp.async.wait_group 1;\n" ::: "memory");
        else
            asm volatile("cp.async.wait_group 0;\n" ::: "memory");
        __syncthreads();

        // Issue next-next stage load (into the slot computed last iteration)
        if (kt + 2 < ktiles) load_stage((kt + 2) % 3, kt + 2);

        const uint32_t aBase = sbase + (kt % 3) * 49152;
        const uint32_t bBase = aBase + 16384;

        #pragma unroll
        for (int kk = 0; kk < 4; kk++) {
            uint32_t a[4][4], b[4][4];
            #pragma unroll
            for (int mf = 0; mf < 4; mf++) {
                uint32_t row = warp_m * 64 + mf * 16 + (lane & 15);
                uint32_t chunk = kk * 2 + (lane >> 4);
                asm volatile("ldmatrix.sync.aligned.m8n8.x4.shared.b16 {%0,%1,%2,%3}, [%4];\n"
                    : "=r"(a[mf][0]), "=r"(a[mf][1]), "=r"(a[mf][2]), "=r"(a[mf][3])
                    : "r"(aBase + swz(row, chunk)));
            }
            #pragma unroll
            for (int q = 0; q < 4; q++) {
                // matrices: {n0-7 k-even, n0-7 k-odd, n8-15 k-even, n8-15 k-odd}
                uint32_t row = warp_n * 64 + q * 16 + ((lane >> 4) << 3) + (lane & 7);
                uint32_t chunk = kk * 2 + ((lane >> 3) & 1);
                asm volatile("ldmatrix.sync.aligned.m8n8.x4.shared.b16 {%0,%1,%2,%3}, [%4];\n"
                    : "=r"(b[q][0]), "=r"(b[q][1]), "=r"(b[q][2]), "=r"(b[q][3])
                    : "r"(bBase + swz(row, chunk)));
            }
            #pragma unroll
            for (int mf = 0; mf < 4; mf++)
                #pragma unroll
                for (int q = 0; q < 4; q++) {
                    asm volatile(
                        "mma.sync.aligned.m16n8k16.row.col.f32.bf16.bf16.f32 "
                        "{%0,%1,%2,%3}, {%4,%5,%6,%7}, {%8,%9}, {%0,%1,%2,%3};\n"
                        : "+f"(acc[mf][2*q][0]), "+f"(acc[mf][2*q][1]),
                          "+f"(acc[mf][2*q][2]), "+f"(acc[mf][2*q][3])
                        : "r"(a[mf][0]), "r"(a[mf][1]), "r"(a[mf][2]), "r"(a[mf][3]),
                          "r"(b[q][0]), "r"(b[q][1]));
                    asm volatile(
                        "mma.sync.aligned.m16n8k16.row.col.f32.bf16.bf16.f32 "
                        "{%0,%1,%2,%3}, {%4,%5,%6,%7}, {%8,%9}, {%0,%1,%2,%3};\n"
                        : "+f"(acc[mf][2*q+1][0]), "+f"(acc[mf][2*q+1][1]),
                          "+f"(acc[mf][2*q+1][2]), "+f"(acc[mf][2*q+1][3])
                        : "r"(a[mf][0]), "r"(a[mf][1]), "r"(a[mf][2]), "r"(a[mf][3]),
                          "r"(b[q][2]), "r"(b[q][3]));
                }
        }
        __syncthreads();
    }

    // Epilogue: bf16 stores (reference bf16 quantization grid)
    const int row_in = lane >> 2;
    const int col_in = (lane & 3) * 2;
    #pragma unroll
    for (int mf = 0; mf < 4; mf++) {
        #pragma unroll
        for (int nf = 0; nf < 8; nf++) {
            int n0 = m0 + warp_m * 64 + mf * 16 + row_in;
            int v  = v0 + warp_n * 64 + nf * 8 + col_in;
            __nv_bfloat16* r0 = C + (size_t)n0 * VPAD;
            __nv_bfloat16* r1 = C + (size_t)(n0 + 8) * VPAD;
            if (v + 1 < VDIM) {
                *(__nv_bfloat162*)(r0 + v) = __floats2bfloat162_rn(acc[mf][nf][0], acc[mf][nf][1]);
                *(__nv_bfloat162*)(r1 + v) = __floats2bfloat162_rn(acc[mf][nf][2], acc[mf][nf][3]);
            } else if (v < VDIM) {
                r0[v] = __float2bfloat16_rn(acc[mf][nf][0]);
                r1[v] = __float2bfloat16_rn(acc[mf][nf][2]);
            }
        }
    }
}

// ---------------------------------------------------------------------------
// Fused per-row loss: pass 1 = online lse (both rows); pass 2 (L2-hot) = JSD.
// ---------------------------------------------------------------------------
#define NPAIR (VDIM / 2)   // 25128; tail element VDIM-1 by thread 0
__global__ __launch_bounds__(256) void rowloss_kernel(const int* __restrict__ target) {
    const int n = blockIdx.x;
    const __nv_bfloat16* rs = g_logits_s + (size_t)n * VPAD;
    const __nv_bfloat16* rt = g_logits_t + (size_t)n * VPAD;
    const __nv_bfloat162* rs2 = (const __nv_bfloat162*)rs;
    const __nv_bfloat162* rt2 = (const __nv_bfloat162*)rt;

    __shared__ float sh0[256], sh1[256], sh2[256], sh3[256];
    __shared__ float s_ls, s_lt;

    float ms = -INFINITY, ss = 0.f, mt = -INFINITY, st = 0.f;
    for (int p = threadIdx.x; p < NPAIR; p += 256) {
        __nv_bfloat162 xs2 = rs2[p], xt2 = rt2[p];
        float s0 = __bfloat162float(xs2.x), s1 = __bfloat162float(xs2.y);
        float t0 = __bfloat162float(xt2.x), t1 = __bfloat162float(xt2.y);
        float nms = fmaxf(ms, fmaxf(s0, s1));
        ss = ss * __expf(ms - nms) + __expf(s0 - nms) + __expf(s1 - nms);
        ms = nms;
        float nmt = fmaxf(mt, fmaxf(t0, t1));
        st = st * __expf(mt - nmt) + __expf(t0 - nmt) + __expf(t1 - nmt);
        mt = nmt;
    }
    if (threadIdx.x == 0) {
        float s0 = __bfloat162float(rs[VDIM - 1]);
        float nms = fmaxf(ms, s0);
        ss = ss * __expf(ms - nms) + __expf(s0 - nms); ms = nms;
        float t0 = __bfloat162float(rt[VDIM - 1]);
        float nmt = fmaxf(mt, t0);
        st = st * __expf(mt - nmt) + __expf(t0 - nmt); mt = nmt;
    }
    sh0[threadIdx.x] = ms; sh1[threadIdx.x] = ss;
    sh2[threadIdx.x] = mt; sh3[threadIdx.x] = st;
    __syncthreads();
    for (int off = 128; off > 0; off >>= 1) {
        if (threadIdx.x < off) {
            float m2 = sh0[threadIdx.x + off], s2 = sh1[threadIdx.x + off];
            float m1 = sh0[threadIdx.x],       s1 = sh1[threadIdx.x];
            float nm = fmaxf(m1, m2);
            sh1[threadIdx.x] = s1 * __expf(m1 - nm) + s2 * __expf(m2 - nm);
            sh0[threadIdx.x] = nm;
            m2 = sh2[threadIdx.x + off]; s2 = sh3[threadIdx.x + off];
            m1 = sh2[threadIdx.x];       s1 = sh3[threadIdx.x];
            nm = fmaxf(m1, m2);
            sh3[threadIdx.x] = s1 * __expf(m1 - nm) + s2 * __expf(m2 - nm);
            sh2[threadIdx.x] = nm;
        }
        __syncthreads();
    }
    if (threadIdx.x == 0) {
        s_ls = sh0[0] + __logf(sh1[0]);
        s_lt = sh2[0] + __logf(sh3[0]);
    }
    __syncthreads();
    const float ls = s_ls, lt = s_lt;

    float as = 0.f, at = 0.f;
    for (int p = threadIdx.x; p < NPAIR; p += 256) {
        __nv_bfloat162 s2v = rs2[p], t2v = rt2[p];
        #pragma unroll
        for (int h = 0; h < 2; h++) {
            float sv = __bfloat162float(h ? s2v.y : s2v.x);
            float tv = __bfloat162float(h ? t2v.y : t2v.x);
            float slp = sv - ls, tlp = tv - lt;
            float sp = __expf(slp), tp = __expf(tlp);
            float lm = __logf(0.5f * sp + 0.5f * tp);   // BETA = 0.5
            as += sp * (slp - lm);
            at += tp * (tlp - lm);
        }
    }
    if (threadIdx.x == 0) {
        float slp = __bfloat162float(rs[VDIM - 1]) - ls;
        float tlp = __bfloat162float(rt[VDIM - 1]) - lt;
        float sp = __expf(slp), tp = __expf(tlp);
        float lm = __logf(0.5f * sp + 0.5f * tp);
        as += sp * (slp - lm);
        at += tp * (tlp - lm);
    }
    sh0[threadIdx.x] = as; sh1[threadIdx.x] = at;
    __syncthreads();
    for (int off = 128; off > 0; off >>= 1) {
        if (threadIdx.x < off) {
            sh0[threadIdx.x] += sh0[threadIdx.x + off];
            sh1[threadIdx.x] += sh1[threadIdx.x + off];
        }
        __syncthreads();
    }
    if (threadIdx.x == 0) {
        g_row_kls[n] = sh0[0];
        g_row_klt[n] = sh1[0];
        int tg = target[n];
        bool valid = (tg != -100);
        int tgs = valid ? tg : 0;
        g_row_ce[n]    = valid ? (ls - __bfloat162float(rs[tgs])) : 0.f;
        g_row_valid[n] = valid ? 1.f : 0.f;
    }
}

// ---------------------------------------------------------------------------
// Final combine -> scalar loss (deterministic).
// ---------------------------------------------------------------------------
__global__ __launch_bounds__(256) void combine_kernel(float* __restrict__ out) {
    __shared__ float s0[256], s1[256], s2[256], s3[256];
    float a = 0.f, b = 0.f, c = 0.f, d = 0.f;
    for (int n = threadIdx.x; n < NROWS; n += 256) {
        a += g_row_ce[n];
        b += g_row_valid[n];
        c += g_row_kls[n];
        d += g_row_klt[n];
    }
    s0[threadIdx.x] = a; s1[threadIdx.x] = b; s2[threadIdx.x] = c; s3[threadIdx.x] = d;
    __syncthreads();
    for (int off = 128; off > 0; off >>= 1) {
        if (threadIdx.x < off) {
            s0[threadIdx.x] += s0[threadIdx.x + off];
            s1[threadIdx.x] += s1[threadIdx.x + off];
            s2[threadIdx.x] += s2[threadIdx.x + off];
            s3[threadIdx.x] += s3[threadIdx.x + off];
        }
        __syncthreads();
    }
    if (threadIdx.x == 0) {
        float hard = s0[0] / s1[0];
        float jsd  = (0.5f * s3[0] + 0.5f * s2[0]) / (float)NROWS;  // BETA=0.5
        out[0] = 0.5f * hard + 0.5f * jsd;
    }
}

// ---------------------------------------------------------------------------
// Launch.  Inputs are FLOAT32 (harness widens bf16); identified by size.
// ---------------------------------------------------------------------------
extern "C" void kernel_launch(void* const* d_in, const int* in_sizes, int n_in,
                              void* d_out, int out_size) {
    const float* student = nullptr;
    const float* W_s     = nullptr;
    const float* teacher = nullptr;
    const float* W_t     = nullptr;
    const int*   target  = nullptr;

    for (int i = 0; i < n_in; i++) {
        long sz = in_sizes[i];
        if      (sz == (long)NROWS * H_S)      student = (const float*)d_in[i];
        else if (sz == (long)VDIM  * H_S)      W_s     = (const float*)d_in[i];
        else if (sz == (long)NROWS * H_T)      teacher = (const float*)d_in[i];
        else if (sz == (long)VDIM  * H_T)      W_t     = (const float*)d_in[i];
        else if (sz == (long)NROWS)            target  = (const int*)d_in[i];
    }

    __nv_bfloat16 *Cs, *Ct, *Wsb, *Wtb, *asb, *atb;
    cudaGetSymbolAddress((void**)&Cs,  g_logits_s);
    cudaGetSymbolAddress((void**)&Ct,  g_logits_t);
    cudaGetSymbolAddress((void**)&Wsb, g_Ws_bf);
    cudaGetSymbolAddress((void**)&Wtb, g_Wt_bf);
    cudaGetSymbolAddress((void**)&asb, g_as_bf);
    cudaGetSymbolAddress((void**)&atb, g_at_bf);

    cudaFuncSetAttribute(gemm_bf16_kernel,
                         cudaFuncAttributeMaxDynamicSharedMemorySize, 147456);

    // fp32 -> bf16 (lossless)
    cvt_kernel<<<4096, 256>>>(W_s,     Wsb, (size_t)VDIM  * H_S / 4);
    cvt_kernel<<<4096, 256>>>(W_t,     Wtb, (size_t)VDIM  * H_T / 4);
    cvt_kernel<<<1024, 256>>>(student, asb, (size_t)NROWS * H_S / 4);
    cvt_kernel<<<1024, 256>>>(teacher, atb, (size_t)NROWS * H_T / 4);

    dim3 ggrid(NROWS / 128, (VDIM + 255) / 256);   // (16, 197), M innermost
    gemm_bf16_kernel<<<ggrid, 256, 147456>>>(asb, Wsb, Cs, H_S);
    gemm_bf16_kernel<<<ggrid, 256, 147456>>>(atb, Wtb, Ct, H_T);

    rowloss_kernel<<<NROWS, 256>>>(target);
    combine_kernel<<<1, 256>>>((float*)d_out);
}